// round 3
// baseline (speedup 1.0000x reference)
#include <cuda_runtime.h>
#include <cuda_bf16.h>
#include <stdint.h>

// Problem dims
#define BDIM 32
#define TDIM 512
#define IDIM 512
#define HDIM 1024
#define MDIM (TDIM * BDIM)   // 16384 rows (m = t*B + b)

// ---------------- scratch (static device globals; no allocation) ----------------
__device__ float g_xT[(size_t)MDIM * IDIM];   // x transposed to [t,b,i] rows
__device__ float g_xw[(size_t)MDIM * HDIM];   // xw0, later reused as xw1
__device__ float g_h1[(size_t)MDIM * HDIM];   // layer-0 hidden states [t,b,h]

__device__ unsigned g_flags0[128];            // layer-0 producer progress (step count)
__device__ unsigned g_flags1[128];            // layer-1 producer progress

// ---------------- f32x2 helpers ----------------
__device__ __forceinline__ void ffma2(unsigned long long& d,
                                      unsigned long long a,
                                      unsigned long long b) {
    asm("fma.rn.f32x2 %0, %1, %2, %0;" : "+l"(d) : "l"(a), "l"(b));
}
__device__ __forceinline__ unsigned long long splat2(float x) {
    unsigned long long r;
    asm("mov.b64 %0, {%1, %1};" : "=l"(r) : "f"(x));
    return r;
}
__device__ __forceinline__ float2 unpack2(unsigned long long v) {
    float lo, hi;
    asm("mov.b64 {%0, %1}, %2;" : "=f"(lo), "=f"(hi) : "l"(v));
    return make_float2(lo, hi);
}
__device__ __forceinline__ ulonglong2 ldcg_u64x2(const void* p) {
    ulonglong2 v;
    asm volatile("ld.global.cg.v2.u64 {%0,%1}, [%2];"
                 : "=l"(v.x), "=l"(v.y) : "l"(p));
    return v;
}

// ---------------- init flags (runs inside the graph, every replay) ----------------
__global__ void init_flags() {
    if (threadIdx.x < 128) {
        g_flags0[threadIdx.x] = 0;
        g_flags1[threadIdx.x] = 0;
    }
}

// ---------------- transpose x[B,T,I] -> xT[(t*B+b), I] ----------------
__global__ __launch_bounds__(128) void transpose_x(const float* __restrict__ x) {
    int m = blockIdx.x;            // 0..MDIM-1
    int t = m >> 5;                // m / 32
    int b = m & 31;
    const float4* src = (const float4*)(x + ((size_t)b * TDIM + t) * IDIM);
    float4* dst = (float4*)(g_xT + (size_t)m * IDIM);
    dst[threadIdx.x] = src[threadIdx.x];   // 128 threads * float4 = 512 floats
}

// ---------------- SGEMM: C[M,1024] = A[M,K] @ W[1024,K]^T + (b1+b2) ----------------
// 128x128 tile, BK=8, 256 threads, 8x8 per thread, FFMA2 inner loop.
#define GBK 8
#define SAP 132   // padded smem stride

__global__ __launch_bounds__(256) void gemm_bias(
    const float* __restrict__ A, const float* __restrict__ W,
    const float* __restrict__ b1, const float* __restrict__ b2,
    float* __restrict__ C, int K)
{
    __shared__ __align__(16) float As[GBK * SAP];
    __shared__ __align__(16) float Bs[GBK * SAP];

    int tid  = threadIdx.x;
    int tx   = tid & 15;          // 0..15 -> N
    int ty   = tid >> 4;          // 0..15 -> M
    int brow = blockIdx.y * 128;  // M offset
    int bcol = blockIdx.x * 128;  // N offset

    int lr = tid >> 1;            // 0..127 loader row
    int lk = (tid & 1) * 4;       // 0 or 4

    const float* Aptr = A + (size_t)(brow + lr) * K + lk;
    const float* Wptr = W + (size_t)(bcol + lr) * K + lk;

    unsigned long long accp[4][8];
    #pragma unroll
    for (int p = 0; p < 4; p++)
        #pragma unroll
        for (int j = 0; j < 8; j++) accp[p][j] = 0ull;

    for (int k0 = 0; k0 < K; k0 += GBK) {
        float4 av = *(const float4*)(Aptr + k0);
        float4 wv = *(const float4*)(Wptr + k0);
        As[(lk + 0) * SAP + lr] = av.x;
        As[(lk + 1) * SAP + lr] = av.y;
        As[(lk + 2) * SAP + lr] = av.z;
        As[(lk + 3) * SAP + lr] = av.w;
        Bs[(lk + 0) * SAP + lr] = wv.x;
        Bs[(lk + 1) * SAP + lr] = wv.y;
        Bs[(lk + 2) * SAP + lr] = wv.z;
        Bs[(lk + 3) * SAP + lr] = wv.w;
        __syncthreads();

        #pragma unroll
        for (int kk = 0; kk < GBK; kk++) {
            const float* abase = &As[kk * SAP + ty * 8];
            ulonglong2 a01 = *(const ulonglong2*)abase;
            ulonglong2 a23 = *(const ulonglong2*)(abase + 4);
            unsigned long long ap[4] = {a01.x, a01.y, a23.x, a23.y};

            const float* bbase = &Bs[kk * SAP + tx * 8];
            float4 bv0 = *(const float4*)bbase;
            float4 bv1 = *(const float4*)(bbase + 4);
            unsigned long long bsp[8] = {
                splat2(bv0.x), splat2(bv0.y), splat2(bv0.z), splat2(bv0.w),
                splat2(bv1.x), splat2(bv1.y), splat2(bv1.z), splat2(bv1.w)};

            #pragma unroll
            for (int p = 0; p < 4; p++)
                #pragma unroll
                for (int j = 0; j < 8; j++)
                    ffma2(accp[p][j], ap[p], bsp[j]);
        }
        __syncthreads();
    }

    float bs[8];
    #pragma unroll
    for (int j = 0; j < 8; j++) {
        int col = bcol + tx * 8 + j;
        bs[j] = __ldg(b1 + col) + __ldg(b2 + col);
    }

    #pragma unroll
    for (int p = 0; p < 4; p++) {
        float2 u[8];
        #pragma unroll
        for (int j = 0; j < 8; j++) u[j] = unpack2(accp[p][j]);

        int row0 = brow + ty * 8 + 2 * p;
        float* cp0 = C + (size_t)row0 * HDIM + bcol + tx * 8;
        float* cp1 = cp0 + HDIM;
        float4 o;
        o.x = u[0].x + bs[0]; o.y = u[1].x + bs[1];
        o.z = u[2].x + bs[2]; o.w = u[3].x + bs[3];
        *(float4*)(cp0) = o;
        o.x = u[4].x + bs[4]; o.y = u[5].x + bs[5];
        o.z = u[6].x + bs[6]; o.w = u[7].x + bs[7];
        *(float4*)(cp0 + 4) = o;
        o.x = u[0].y + bs[0]; o.y = u[1].y + bs[1];
        o.z = u[2].y + bs[2]; o.w = u[3].y + bs[3];
        *(float4*)(cp1) = o;
        o.x = u[4].y + bs[4]; o.y = u[5].y + bs[5];
        o.z = u[6].y + bs[6]; o.w = u[7].y + bs[7];
        *(float4*)(cp1 + 4) = o;
    }
}

// ---------------- dataflow recurrence ----------------
// 128 CTAs x 128 threads. CTA cb owns output columns [8cb, 8cb+8).
// Thread (j = tid&7, p = tid>>3) computes columns col=8cb+j for batches
// b0=2p, b1=2p+1 (2 outputs/thread -> w row read once per 2 dot products).
// Whh slice (8x1024) resident in smem; h_{t-1} read directly from global
// via ld.global.cg (L2 broadcast). No grid barrier: per-producer monotonic
// flags (release/acquire) gate each step's reads.
#define RPAD 1028   // padded float stride (4112 B, 16B-aligned, conflict-free)

__global__ __launch_bounds__(128) void recur2(
    const float* __restrict__ xw,   // [t*B+b, H] input projection (+biases)
    const float* __restrict__ Whh,  // [H, H]
    float* __restrict__ hio,        // layer0: g_h1 [t,b,h] ; layer1: d_out [b,t,h]
    unsigned* __restrict__ flags,   // 128 producer flags
    int bth)                        // 0 -> [T,B,H] layout, 1 -> [B,T,H]
{
    __shared__ __align__(16) float Ws[8 * RPAD];

    int tid = threadIdx.x;
    int cb  = blockIdx.x;           // 0..127
    int j   = tid & 7;
    int p   = tid >> 3;             // 0..15
    int b0  = 2 * p;
    int b1  = 2 * p + 1;
    int col = cb * 8 + j;

    // load this CTA's 8 weight rows into smem
    for (int idx = tid; idx < 8 * 256; idx += 128) {
        int row = idx >> 8;
        int kq  = idx & 255;
        float4 w = *(const float4*)(Whh + (size_t)(cb * 8 + row) * HDIM + kq * 4);
        *(float4*)&Ws[row * RPAD + kq * 4] = w;
    }
    __syncthreads();

    const ulonglong2* wrow = (const ulonglong2*)&Ws[j * RPAD];

    for (int t = 0; t < TDIM; t++) {
        // xw loads are independent of h: issue before the flag wait
        float xv0 = __ldg(xw + ((size_t)t * BDIM + b0) * HDIM + col);
        float xv1 = __ldg(xw + ((size_t)t * BDIM + b1) * HDIM + col);
        float o0, o1;

        if (t == 0) {
            o0 = xv0;
            o1 = xv1;
        } else {
            // wait until every producer has published step t-1 (flag >= t)
            unsigned f;
            do {
                asm volatile("ld.acquire.gpu.u32 %0, [%1];"
                             : "=r"(f) : "l"(flags + tid));
            } while (f < (unsigned)t);
            __syncthreads();   // all 128 flags seen -> h_{t-1} fully visible

            size_t rb0 = bth ? ((size_t)b0 * TDIM + (t - 1)) * HDIM
                             : ((size_t)(t - 1) * BDIM + b0) * HDIM;
            size_t rb1 = bth ? ((size_t)b1 * TDIM + (t - 1)) * HDIM
                             : ((size_t)(t - 1) * BDIM + b1) * HDIM;
            const char* h0p = (const char*)(hio + rb0);
            const char* h1p = (const char*)(hio + rb1);

            unsigned long long a00 = 0ull, a01 = 0ull, a10 = 0ull, a11 = 0ull;
            #pragma unroll 4
            for (int kq = 0; kq < 256; kq++) {
                ulonglong2 wv = wrow[kq];
                ulonglong2 h0 = ldcg_u64x2(h0p + 16 * kq);
                ulonglong2 h1 = ldcg_u64x2(h1p + 16 * kq);
                ffma2(a00, h0.x, wv.x);
                ffma2(a01, h0.y, wv.y);
                ffma2(a10, h1.x, wv.x);
                ffma2(a11, h1.y, wv.y);
            }
            float2 u0 = unpack2(a00), u1 = unpack2(a01);
            float2 u2 = unpack2(a10), u3 = unpack2(a11);
            o0 = xv0 + ((u0.x + u0.y) + (u1.x + u1.y));
            o1 = xv1 + ((u2.x + u2.y) + (u3.x + u3.y));
        }

        float hv0 = tanhf(o0);
        float hv1 = tanhf(o1);

        size_t d0 = bth ? ((size_t)b0 * TDIM + t) * HDIM + col
                        : ((size_t)t * BDIM + b0) * HDIM + col;
        size_t d1 = bth ? ((size_t)b1 * TDIM + t) * HDIM + col
                        : ((size_t)t * BDIM + b1) * HDIM + col;
        hio[d0] = hv0;
        hio[d1] = hv1;

        __syncthreads();   // all 256 outputs of this CTA stored
        if (tid == 0) {
            asm volatile("st.release.gpu.u32 [%0], %1;"
                         :: "l"(flags + cb), "r"((unsigned)(t + 1)));
        }
    }
}

// ---------------- launch ----------------
extern "C" void kernel_launch(void* const* d_in, const int* in_sizes, int n_in,
                              void* d_out, int out_size)
{
    const float* x    = (const float*)d_in[0];
    const float* Wih0 = (const float*)d_in[1];
    const float* Whh0 = (const float*)d_in[2];
    const float* bih0 = (const float*)d_in[3];
    const float* bhh0 = (const float*)d_in[4];
    const float* Wih1 = (const float*)d_in[5];
    const float* Whh1 = (const float*)d_in[6];
    const float* bih1 = (const float*)d_in[7];
    const float* bhh1 = (const float*)d_in[8];
    float* out = (float*)d_out;

    float *xT, *xw, *h1;
    unsigned *f0, *f1;
    cudaGetSymbolAddress((void**)&xT, g_xT);
    cudaGetSymbolAddress((void**)&xw, g_xw);
    cudaGetSymbolAddress((void**)&h1, g_h1);
    cudaGetSymbolAddress((void**)&f0, g_flags0);
    cudaGetSymbolAddress((void**)&f1, g_flags1);

    // 0) reset flags (inside the graph -> replayed every run)
    init_flags<<<1, 128>>>();

    // 1) transpose x -> xT[(t*B+b), I]
    transpose_x<<<MDIM, 128>>>(x);

    // 2) xw0 = xT @ Wih0^T + (bih0 + bhh0)
    gemm_bias<<<dim3(HDIM / 128, MDIM / 128), 256>>>(xT, Wih0, bih0, bhh0, xw, IDIM);

    // 3) layer-0 recurrence -> h1 [t,b,h]
    recur2<<<128, 128>>>(xw, Whh0, h1, f0, 0);

    // 4) xw1 = h1 @ Wih1^T + (bih1 + bhh1)
    gemm_bias<<<dim3(HDIM / 128, MDIM / 128), 256>>>(h1, Wih1, bih1, bhh1, xw, HDIM);

    // 5) layer-1 recurrence -> d_out [b,t,h]
    recur2<<<128, 128>>>(xw, Whh1, out, f1, 1);
}

// round 4
// speedup vs baseline: 2.2734x; 2.2734x over previous
#include <cuda_runtime.h>
#include <cuda_bf16.h>
#include <stdint.h>

typedef unsigned long long ull;

// Problem dims
#define BDIM 32
#define TDIM 512
#define IDIM 512
#define HDIM 1024
#define MDIM (TDIM * BDIM)   // 16384 rows (m = t*B + b)

// ---------------- scratch (static device globals; no allocation) ----------------
__device__ float g_xT[(size_t)MDIM * IDIM];   // x transposed to [t,b,i] rows
__device__ float g_xw[(size_t)MDIM * HDIM];   // xw0, later reused as xw1
__device__ float g_h1[(size_t)MDIM * HDIM];   // layer-0 hidden states [t,b,h]
__device__ float g_hT[2][HDIM][BDIM];         // ping-pong transposed h (128KB each)

__device__ unsigned g_flags0[128];
__device__ unsigned g_flags1[128];

// ---------------- f32x2 helpers ----------------
__device__ __forceinline__ void ffma2(ull& d, ull a, ull b) {
    asm("fma.rn.f32x2 %0, %1, %2, %0;" : "+l"(d) : "l"(a), "l"(b));
}
__device__ __forceinline__ void add2(ull& d, ull a) {
    asm("add.rn.f32x2 %0, %0, %1;" : "+l"(d) : "l"(a));
}
__device__ __forceinline__ ull splat2(float x) {
    ull r;
    asm("mov.b64 %0, {%1, %1};" : "=l"(r) : "f"(x));
    return r;
}
__device__ __forceinline__ float2 unpack2(ull v) {
    float lo, hi;
    asm("mov.b64 {%0, %1}, %2;" : "=f"(lo), "=f"(hi) : "l"(v));
    return make_float2(lo, hi);
}
__device__ __forceinline__ ull pack2(float lo, float hi) {
    ull r;
    asm("mov.b64 %0, {%1, %2};" : "=l"(r) : "f"(lo), "f"(hi));
    return r;
}
__device__ __forceinline__ ulonglong2 ldcg16(const void* p) {
    ulonglong2 v;
    asm volatile("ld.global.cg.v2.u64 {%0,%1}, [%2];"
                 : "=l"(v.x), "=l"(v.y) : "l"(p));
    return v;
}

// ---------------- init flags (inside graph; replayed every run) ----------------
__global__ void init_flags() {
    if (threadIdx.x < 128) {
        g_flags0[threadIdx.x] = 0;
        g_flags1[threadIdx.x] = 0;
    }
}

// ---------------- transpose x[B,T,I] -> xT[(t*B+b), I] ----------------
__global__ __launch_bounds__(128) void transpose_x(const float* __restrict__ x) {
    int m = blockIdx.x;
    int t = m >> 5;
    int b = m & 31;
    const float4* src = (const float4*)(x + ((size_t)b * TDIM + t) * IDIM);
    float4* dst = (float4*)(g_xT + (size_t)m * IDIM);
    dst[threadIdx.x] = src[threadIdx.x];
}

// ---------------- SGEMM: C[M,1024] = A[M,K] @ W[1024,K]^T + (b1+b2) ----------------
#define GBK 8
#define SAP 132

__global__ __launch_bounds__(256) void gemm_bias(
    const float* __restrict__ A, const float* __restrict__ W,
    const float* __restrict__ b1, const float* __restrict__ b2,
    float* __restrict__ C, int K)
{
    __shared__ __align__(16) float As[GBK * SAP];
    __shared__ __align__(16) float Bs[GBK * SAP];

    int tid  = threadIdx.x;
    int tx   = tid & 15;
    int ty   = tid >> 4;
    int brow = blockIdx.y * 128;
    int bcol = blockIdx.x * 128;

    int lr = tid >> 1;
    int lk = (tid & 1) * 4;

    const float* Aptr = A + (size_t)(brow + lr) * K + lk;
    const float* Wptr = W + (size_t)(bcol + lr) * K + lk;

    ull accp[4][8];
    #pragma unroll
    for (int p = 0; p < 4; p++)
        #pragma unroll
        for (int j = 0; j < 8; j++) accp[p][j] = 0ull;

    for (int k0 = 0; k0 < K; k0 += GBK) {
        float4 av = *(const float4*)(Aptr + k0);
        float4 wv = *(const float4*)(Wptr + k0);
        As[(lk + 0) * SAP + lr] = av.x;
        As[(lk + 1) * SAP + lr] = av.y;
        As[(lk + 2) * SAP + lr] = av.z;
        As[(lk + 3) * SAP + lr] = av.w;
        Bs[(lk + 0) * SAP + lr] = wv.x;
        Bs[(lk + 1) * SAP + lr] = wv.y;
        Bs[(lk + 2) * SAP + lr] = wv.z;
        Bs[(lk + 3) * SAP + lr] = wv.w;
        __syncthreads();

        #pragma unroll
        for (int kk = 0; kk < GBK; kk++) {
            const float* abase = &As[kk * SAP + ty * 8];
            ulonglong2 a01 = *(const ulonglong2*)abase;
            ulonglong2 a23 = *(const ulonglong2*)(abase + 4);
            ull ap[4] = {a01.x, a01.y, a23.x, a23.y};

            const float* bbase = &Bs[kk * SAP + tx * 8];
            float4 bv0 = *(const float4*)bbase;
            float4 bv1 = *(const float4*)(bbase + 4);
            ull bsp[8] = {
                splat2(bv0.x), splat2(bv0.y), splat2(bv0.z), splat2(bv0.w),
                splat2(bv1.x), splat2(bv1.y), splat2(bv1.z), splat2(bv1.w)};

            #pragma unroll
            for (int p = 0; p < 4; p++)
                #pragma unroll
                for (int j = 0; j < 8; j++)
                    ffma2(accp[p][j], ap[p], bsp[j]);
        }
        __syncthreads();
    }

    float bs[8];
    #pragma unroll
    for (int j = 0; j < 8; j++) {
        int c = bcol + tx * 8 + j;
        bs[j] = __ldg(b1 + c) + __ldg(b2 + c);
    }

    #pragma unroll
    for (int p = 0; p < 4; p++) {
        float2 u[8];
        #pragma unroll
        for (int j = 0; j < 8; j++) u[j] = unpack2(accp[p][j]);

        int row0 = brow + ty * 8 + 2 * p;
        float* cp0 = C + (size_t)row0 * HDIM + bcol + tx * 8;
        float* cp1 = cp0 + HDIM;
        float4 o;
        o.x = u[0].x + bs[0]; o.y = u[1].x + bs[1];
        o.z = u[2].x + bs[2]; o.w = u[3].x + bs[3];
        *(float4*)(cp0) = o;
        o.x = u[4].x + bs[4]; o.y = u[5].x + bs[5];
        o.z = u[6].x + bs[6]; o.w = u[7].x + bs[7];
        *(float4*)(cp0 + 4) = o;
        o.x = u[0].y + bs[0]; o.y = u[1].y + bs[1];
        o.z = u[2].y + bs[2]; o.w = u[3].y + bs[3];
        *(float4*)(cp1) = o;
        o.x = u[4].y + bs[4]; o.y = u[5].y + bs[5];
        o.z = u[6].y + bs[6]; o.w = u[7].y + bs[7];
        *(float4*)(cp1 + 4) = o;
    }
}

// ---------------- k-split recurrence ----------------
// 128 CTAs x 256 threads. CTA cb owns cols [8cb, 8cb+8).
// Thread (kg=tid>>2 in 0..63, s=tid&3): computes partials for all 8 cols x
// batches [8s,8s+8) over k-slice [16kg,16kg+16). h operands are thread-private
// (each hT element read exactly once per CTA, ld.global.cg pipelined).
// W slice in smem, i-major swizzled: Wsm[(k&15)*512 + (k>>4)*8 + j].
// Partials: per-thread 16 x 16B chunks, chunk index XOR-swizzled by (tid&15).
// Reduction: threads 0..127 (j=tid&7, bp=tid>>3) sum 64 k-group partials.
#define RC_SMEM_BYTES (126976)   // 32KB W + 64KB partials, padded -> 1 CTA/SM

__global__ __launch_bounds__(256) void recur3(
    const float* __restrict__ xw,   // [t*B+b, H] input projection (+biases)
    const float* __restrict__ Whh,  // [H, H]
    float* __restrict__ hio,        // layer0: g_h1 [t,b,h] ; layer1: d_out [b,t,h]
    unsigned* __restrict__ flags,   // 128 producer flags
    int bth)
{
    extern __shared__ __align__(16) float sm[];
    float* Wsm = sm;                       // 8192 floats (32KB)
    char*  Psm = (char*)(sm + 8192);       // 64KB partials

    int tid = threadIdx.x;
    int cb  = blockIdx.x;
    int kg  = tid >> 2;     // 0..63
    int s   = tid & 3;      // 0..3

    // reducer coords (tid < 128)
    int j_r  = tid & 7;
    int bp   = tid >> 3;            // 0..15 batch-pair
    int col  = cb * 8 + j_r;
    int sR   = bp >> 2;
    int cR   = ((bp & 3) << 2) + (j_r >> 1);
    int half = j_r & 1;

    // build i-major W layout: Wsm[(k&15)*512 + (k>>4)*8 + j] = Whh[8cb+j][k]
    for (int idx = tid; idx < 8192; idx += 256) {
        int j = idx >> 10;          // 0..7
        int k = idx & 1023;
        Wsm[((k & 15) << 9) + ((k >> 4) << 3) + j] =
            __ldg(Whh + (size_t)(cb * 8 + j) * HDIM + k);
    }
    __syncthreads();

    const char* wbase = (const char*)(Wsm + (size_t)kg * 8);  // + i*2048B per i

    for (int t = 0; t < TDIM; t++) {
        float xv0 = 0.f, xv1 = 0.f;
        if (tid < 128) {
            xv0 = __ldg(xw + ((size_t)t * BDIM + 2 * bp) * HDIM + col);
            xv1 = __ldg(xw + ((size_t)t * BDIM + 2 * bp + 1) * HDIM + col);
        }

        if (t > 0) {
            // wait until every producer published step t-1
            unsigned f;
            do {
                asm volatile("ld.acquire.gpu.u32 %0, [%1];"
                             : "=r"(f) : "l"(flags + (tid & 127)));
            } while (f < (unsigned)t);
            __syncthreads();

            // main compute over private k-slice
            const char* hbase = (const char*)g_hT
                + ((size_t)((t - 1) & 1)) * (HDIM * BDIM * 4)
                + (size_t)kg * 16 * 128 + (size_t)s * 32;

            ull acc[4][8];
            #pragma unroll
            for (int p = 0; p < 4; p++)
                #pragma unroll
                for (int j = 0; j < 8; j++) acc[p][j] = 0ull;

            #pragma unroll
            for (int i = 0; i < 16; i++) {
                ulonglong2 hA = ldcg16(hbase + i * 128);        // bp' 0,1
                ulonglong2 hB = ldcg16(hbase + i * 128 + 16);   // bp' 2,3
                const float4* wp4 = (const float4*)(wbase + i * 2048);
                float4 w0 = wp4[0];
                float4 w1 = wp4[1];
                ull ws[8] = {splat2(w0.x), splat2(w0.y), splat2(w0.z), splat2(w0.w),
                             splat2(w1.x), splat2(w1.y), splat2(w1.z), splat2(w1.w)};
                #pragma unroll
                for (int j = 0; j < 8; j++) {
                    ffma2(acc[0][j], hA.x, ws[j]);
                    ffma2(acc[1][j], hA.y, ws[j]);
                    ffma2(acc[2][j], hB.x, ws[j]);
                    ffma2(acc[3][j], hB.y, ws[j]);
                }
            }

            // store partials (XOR-swizzled 16B chunks)
            #pragma unroll
            for (int p = 0; p < 4; p++)
                #pragma unroll
                for (int m = 0; m < 4; m++) {
                    int c = (p << 2) + m;
                    int a16 = (tid << 4) + (c ^ (tid & 15));
                    ulonglong2 v;
                    v.x = acc[p][2 * m];
                    v.y = acc[p][2 * m + 1];
                    *(ulonglong2*)(Psm + ((size_t)a16 << 4)) = v;
                }
        }
        __syncthreads();   // partials visible (no-op data-wise at t==0)

        if (tid < 128) {
            float o0, o1;
            if (t > 0) {
                ull s0 = 0ull, s1 = 0ull;
                #pragma unroll 4
                for (int k2 = 0; k2 < 64; k2 += 2) {
                    int ta = ((k2)     << 2) + sR;
                    int tb = ((k2 + 1) << 2) + sR;
                    int aa = (ta << 4) + (cR ^ (ta & 15));
                    int ab = (tb << 4) + (cR ^ (tb & 15));
                    ull va = *(const ull*)(Psm + ((size_t)aa << 4) + (half << 3));
                    ull vb = *(const ull*)(Psm + ((size_t)ab << 4) + (half << 3));
                    add2(s0, va);
                    add2(s1, vb);
                }
                add2(s0, s1);
                float2 u = unpack2(s0);
                o0 = xv0 + u.x;
                o1 = xv1 + u.y;
            } else {
                o0 = xv0;
                o1 = xv1;
            }
            float h0 = tanhf(o0);
            float h1 = tanhf(o1);

            int b0 = 2 * bp, b1 = 2 * bp + 1;
            size_t d0, d1;
            if (bth) {
                d0 = ((size_t)b0 * TDIM + t) * HDIM + col;
                d1 = ((size_t)b1 * TDIM + t) * HDIM + col;
            } else {
                d0 = ((size_t)t * BDIM + b0) * HDIM + col;
                d1 = ((size_t)t * BDIM + b1) * HDIM + col;
            }
            hio[d0] = h0;
            hio[d1] = h1;

            // transposed ping-pong store for next step's broadcast
            *(ull*)((char*)g_hT + (size_t)(t & 1) * (HDIM * BDIM * 4)
                    + (size_t)col * 128 + (size_t)bp * 8) = pack2(h0, h1);
        }

        __syncthreads();
        if (tid == 0) {
            asm volatile("st.release.gpu.u32 [%0], %1;"
                         :: "l"(flags + cb), "r"((unsigned)(t + 1)));
        }
    }
}

// ---------------- launch ----------------
extern "C" void kernel_launch(void* const* d_in, const int* in_sizes, int n_in,
                              void* d_out, int out_size)
{
    const float* x    = (const float*)d_in[0];
    const float* Wih0 = (const float*)d_in[1];
    const float* Whh0 = (const float*)d_in[2];
    const float* bih0 = (const float*)d_in[3];
    const float* bhh0 = (const float*)d_in[4];
    const float* Wih1 = (const float*)d_in[5];
    const float* Whh1 = (const float*)d_in[6];
    const float* bih1 = (const float*)d_in[7];
    const float* bhh1 = (const float*)d_in[8];
    float* out = (float*)d_out;

    float *xT, *xw, *h1;
    unsigned *f0, *f1;
    cudaGetSymbolAddress((void**)&xT, g_xT);
    cudaGetSymbolAddress((void**)&xw, g_xw);
    cudaGetSymbolAddress((void**)&h1, g_h1);
    cudaGetSymbolAddress((void**)&f0, g_flags0);
    cudaGetSymbolAddress((void**)&f1, g_flags1);

    cudaFuncSetAttribute(recur3, cudaFuncAttributeMaxDynamicSharedMemorySize,
                         RC_SMEM_BYTES);

    init_flags<<<1, 128>>>();
    transpose_x<<<MDIM, 128>>>(x);
    gemm_bias<<<dim3(HDIM / 128, MDIM / 128), 256>>>(xT, Wih0, bih0, bhh0, xw, IDIM);
    recur3<<<128, 256, RC_SMEM_BYTES>>>(xw, Whh0, h1, f0, 0);
    gemm_bias<<<dim3(HDIM / 128, MDIM / 128), 256>>>(h1, Wih1, bih1, bhh1, xw, HDIM);
    recur3<<<128, 256, RC_SMEM_BYTES>>>(xw, Whh1, out, f1, 1);
}